// round 12
// baseline (speedup 1.0000x reference)
#include <cuda_runtime.h>
#include <cuda_fp16.h>
#include <math.h>

#define NHEADS   12
#define NLH      24          // (latent, head) pairs
#define CHSTRIDE 131072      // elems between channels within a (b,head) plane
#define PLANE    393216      // elems per (b,head) plane = 3*CHSTRIDE
#define LATELEMS 37748736    // elems per latent
#define NPIX_D   1048576.0   // pixels per head (8 * 131072)
#define GROUPS8  131072      // 8-pixel groups per (latent,head)
#define NB0      128         // blocks per (l,h) for pass0
#define NBS      128         // blocks per (l,h) for fp16 moments passes
#define NB4      256         // blocks per head for loss pass
#define BN_EPSF  1e-5f

typedef unsigned long long u64;

// ---------------- packed f32x2 helpers (Blackwell FFMA2 path) ----------------
__device__ __forceinline__ u64 pk2(float lo, float hi) {
  u64 r; asm("mov.b64 %0, {%1, %2};" : "=l"(r) : "f"(lo), "f"(hi)); return r;
}
__device__ __forceinline__ void up2(u64 v, float& lo, float& hi) {
  asm("mov.b64 {%0, %1}, %2;" : "=f"(lo), "=f"(hi) : "l"(v));
}
__device__ __forceinline__ u64 f2fma(u64 a, u64 b, u64 c) {
  u64 d; asm("fma.rn.f32x2 %0, %1, %2, %3;" : "=l"(d) : "l"(a), "l"(b), "l"(c)); return d;
}
__device__ __forceinline__ u64 f2add(u64 a, u64 b) {
  u64 d; asm("add.rn.f32x2 %0, %1, %2;" : "=l"(d) : "l"(a), "l"(b)); return d;
}
__device__ __forceinline__ u64 f2relu(u64 v) {
  float a, b; up2(v, a, b);
  return pk2(fmaxf(a, 0.f), fmaxf(b, 0.f));
}
__device__ __forceinline__ u64 h2f2(__half2 h) {
  float2 f = __half22float2(h); return pk2(f.x, f.y);
}
__device__ __forceinline__ u64 bc2(float f) { return pk2(f, f); }

// ---------------- device scratch (no allocation allowed) ----------------
// BSS zero-initialized at module load; writeout re-zeros for graph replays.
__device__ __align__(16) __half d_x16[2][LATELEMS];   // fp16 staged latents (151MB)
__device__ double d_mom[3][NLH][9];
__device__ double d_loss;

// ---------------- math helpers ----------------
__device__ __forceinline__ void affine_relu_f2(const u64* A, const u64* c,
                                               u64& x0, u64& x1, u64& x2) {
  u64 y0 = f2fma(A[0], x0, f2fma(A[1], x1, f2fma(A[2], x2, c[0])));
  u64 y1 = f2fma(A[3], x0, f2fma(A[4], x1, f2fma(A[5], x2, c[1])));
  u64 y2 = f2fma(A[6], x0, f2fma(A[7], x1, f2fma(A[8], x2, c[2])));
  x0 = f2relu(y0); x1 = f2relu(y1); x2 = f2relu(y2);
}

__device__ __forceinline__ void mom_acc_f2(u64* s, u64 x0, u64 x1, u64 x2) {
  s[0] = f2add(s[0], x0); s[1] = f2add(s[1], x1); s[2] = f2add(s[2], x2);
  s[3] = f2fma(x0, x0, s[3]); s[4] = f2fma(x0, x1, s[4]); s[5] = f2fma(x0, x2, s[5]);
  s[6] = f2fma(x1, x1, s[6]); s[7] = f2fma(x1, x2, s[7]); s[8] = f2fma(x2, x2, s[8]);
}

__device__ __forceinline__ void block_reduce9_f2(const u64* sp, int stage, int lh) {
  float s[9];
  #pragma unroll
  for (int k = 0; k < 9; k++) { float a, b; up2(sp[k], a, b); s[k] = a + b; }
  #pragma unroll
  for (int k = 0; k < 9; k++)
    #pragma unroll
    for (int o = 16; o > 0; o >>= 1) s[k] += __shfl_down_sync(0xffffffffu, s[k], o);
  __shared__ float red[8][9];
  int warp = threadIdx.x >> 5, lane = threadIdx.x & 31;
  if (lane == 0) {
    #pragma unroll
    for (int k = 0; k < 9; k++) red[warp][k] = s[k];
  }
  __syncthreads();
  if (threadIdx.x < 9) {
    float t = 0.f;
    #pragma unroll
    for (int w = 0; w < 8; w++) t += red[w][threadIdx.x];
    atomicAdd(&d_mom[stage][lh][threadIdx.x], (double)t);
  }
}

union Pk { uint4 u; __half2 h[4]; };
__device__ __forceinline__ __half2 pk_h(const uint4& u, int w) {
  Pk p; p.u = u; return p.h[w];
}

// ---------------- inline BN fold (fp32, per-block redundant) ------------------
// From stage moments (9 fp64 sums) + conv/BN params -> affine A[9], cc[3].
// Also returns the stage's mean m[3] and second moment E[9] (for predictor).
__device__ __forceinline__ void fold_stage(const double* Msum,
    const float* __restrict__ W, const float* __restrict__ bb,
    const float* __restrict__ g, const float* __restrict__ be,
    int head, float* A, float* cc, float* m_out, float* E_out) {
  const double inv = 1.0 / NPIX_D;
  float m[3], E[3][3];
  m[0] = (float)(Msum[0] * inv); m[1] = (float)(Msum[1] * inv); m[2] = (float)(Msum[2] * inv);
  E[0][0] = (float)(Msum[3] * inv);
  E[0][1] = E[1][0] = (float)(Msum[4] * inv);
  E[0][2] = E[2][0] = (float)(Msum[5] * inv);
  E[1][1] = (float)(Msum[6] * inv);
  E[1][2] = E[2][1] = (float)(Msum[7] * inv);
  E[2][2] = (float)(Msum[8] * inv);
  #pragma unroll
  for (int o = 0; o < 3; o++) {
    float w[3];
    #pragma unroll
    for (int c = 0; c < 3; c++) w[c] = W[head * 9 + o * 3 + c];
    float bl = bb[head * 3 + o];
    float wm = w[0] * m[0] + w[1] * m[1] + w[2] * m[2];
    float mo = wm + bl;
    float e2 = 0.f;
    #pragma unroll
    for (int c = 0; c < 3; c++)
      #pragma unroll
      for (int d = 0; d < 3; d++) e2 += w[c] * w[d] * E[c][d];
    e2 += 2.f * bl * wm + bl * bl;
    float v = e2 - mo * mo;
    float sc = g[head * 3 + o] / sqrtf(v + BN_EPSF);
    #pragma unroll
    for (int c = 0; c < 3; c++) A[o * 3 + c] = sc * w[c];
    cc[o] = sc * (bl - mo) + be[head * 3 + o];
  }
  if (m_out) { m_out[0] = m[0]; m_out[1] = m[1]; m_out[2] = m[2]; }
  if (E_out) {
    #pragma unroll
    for (int o = 0; o < 3; o++)
      #pragma unroll
      for (int p = 0; p < 3; p++) E_out[o * 3 + p] = E[o][p];
  }
}

// predictor fold: from z = A3*h2+c3 stats (via h2 moments m2,E2) -> h4 = relu(q.z+r)
__device__ __forceinline__ void fold_pred(const float* A3, const float* c3,
    const float* m2, const float* E2,
    const float* __restrict__ W4, const float* __restrict__ b4,
    const float* __restrict__ g4, const float* __restrict__ be4,
    int head, float* q, float& r) {
  float Amh[3], mz[3];
  #pragma unroll
  for (int o = 0; o < 3; o++) {
    Amh[o] = A3[o * 3] * m2[0] + A3[o * 3 + 1] * m2[1] + A3[o * 3 + 2] * m2[2];
    mz[o] = Amh[o] + c3[o];
  }
  float Ezz[3][3];
  #pragma unroll
  for (int o = 0; o < 3; o++)
    #pragma unroll
    for (int p = 0; p < 3; p++) {
      float t = 0.f;
      #pragma unroll
      for (int c = 0; c < 3; c++)
        #pragma unroll
        for (int d = 0; d < 3; d++) t += A3[o * 3 + c] * A3[p * 3 + d] * E2[c * 3 + d];
      Ezz[o][p] = t + c3[o] * Amh[p] + c3[p] * Amh[o] + c3[o] * c3[p];
    }
  float w4[3];
  #pragma unroll
  for (int c = 0; c < 3; c++) w4[c] = W4[head * 3 + c];
  float b4v = b4[head];
  float w4mz = w4[0] * mz[0] + w4[1] * mz[1] + w4[2] * mz[2];
  float mu = w4mz + b4v;
  float eu2 = 0.f;
  #pragma unroll
  for (int c = 0; c < 3; c++)
    #pragma unroll
    for (int d = 0; d < 3; d++) eu2 += w4[c] * w4[d] * Ezz[c][d];
  eu2 += 2.f * b4v * w4mz + b4v * b4v;
  float vu = eu2 - mu * mu;
  float s4 = g4[head] / sqrtf(vu + BN_EPSF);
  #pragma unroll
  for (int c = 0; c < 3; c++) q[c] = s4 * w4[c];
  r = s4 * (b4v - mu) + be4[head];
}

// ---------------- pass 0: fp32 read -> moments of x + fp16 stage-out ----------
__global__ void __launch_bounds__(256) pass0_kernel(const float* __restrict__ lat1,
                                                    const float* __restrict__ lat2) {
  int lh = blockIdx.y;
  int l = lh / NHEADS, head = lh - l * NHEADS;
  const float* __restrict__ src = l ? lat2 : lat1;
  __half* __restrict__ dst = d_x16[l];

  u64 s[9];
  #pragma unroll
  for (int k = 0; k < 9; k++) s[k] = 0ull;

  const int GPB = GROUPS8 / NB0;         // 1024
  const int ITER = GPB / 256;            // 4
  int base_g = blockIdx.x * GPB;

  for (int it = 0; it < ITER; it++) {
    int g  = base_g + it * 256 + threadIdx.x;
    int b  = g >> 14;
    int pg = (g & 16383) << 3;
    size_t po = (size_t)(b * NHEADS + head) * PLANE + pg;
    Pk pk[3];
    #pragma unroll
    for (int c = 0; c < 3; c++) {
      float4 v0 = __ldg((const float4*)(src + po + c * CHSTRIDE));
      float4 v1 = __ldg((const float4*)(src + po + c * CHSTRIDE + 4));
      pk[c].h[0] = __floats2half2_rn(v0.x, v0.y);
      pk[c].h[1] = __floats2half2_rn(v0.z, v0.w);
      pk[c].h[2] = __floats2half2_rn(v1.x, v1.y);
      pk[c].h[3] = __floats2half2_rn(v1.z, v1.w);
      *(uint4*)(dst + po + c * CHSTRIDE) = pk[c].u;
    }
    #pragma unroll
    for (int w = 0; w < 4; w++) {
      u64 x0 = h2f2(pk[0].h[w]);
      u64 x1 = h2f2(pk[1].h[w]);
      u64 x2 = h2f2(pk[2].h[w]);
      mom_acc_f2(s, x0, x1, x2);
    }
  }
  block_reduce9_f2(s, 0, lh);
}

// ---------------- fp16-data moments passes, inline fold, f32x2 math -----------
// REV flips traversal for zig-zag L2 reuse with the previous pass.
template <int S, bool REV>
__global__ void __launch_bounds__(256) momentsH_kernel(
    const float* __restrict__ W1, const float* __restrict__ b1,
    const float* __restrict__ g1, const float* __restrict__ be1,
    const float* __restrict__ W2, const float* __restrict__ b2,
    const float* __restrict__ g2, const float* __restrict__ be2) {
  int bid = blockIdx.y * NBS + blockIdx.x;
  if (REV) bid = NBS * NLH - 1 - bid;
  int lh = bid / NBS, bx = bid % NBS;
  const __half* __restrict__ src = d_x16[lh / NHEADS];
  int head = lh % NHEADS;

  const int GPB = GROUPS8 / NBS;         // 1024
  const int ITER = GPB / 256;            // 4
  int base_g = bx * GPB;

  // issue first iteration's loads before the fold chain (hide fold latency)
  uint4 cu0[3];
  {
    int g = base_g + threadIdx.x;
    int b = g >> 14;
    int pg = (g & 16383) << 3;
    size_t po = (size_t)(b * NHEADS + head) * PLANE + pg;
    #pragma unroll
    for (int c = 0; c < 3; c++) cu0[c] = __ldg((const uint4*)(src + po + c * CHSTRIDE));
  }

  // inline fold (fp32, redundant per thread)
  float A1f[9], c1f[3], A2f[9], c2f[3];
  fold_stage(d_mom[0][lh], W1, b1, g1, be1, head, A1f, c1f, nullptr, nullptr);
  if (S >= 2) fold_stage(d_mom[1][lh], W2, b2, g2, be2, head, A2f, c2f, nullptr, nullptr);

  u64 A1[9], c1[3], A2[9], c2[3];
  #pragma unroll
  for (int k = 0; k < 9; k++) A1[k] = bc2(A1f[k]);
  #pragma unroll
  for (int k = 0; k < 3; k++) c1[k] = bc2(c1f[k]);
  if (S >= 2) {
    #pragma unroll
    for (int k = 0; k < 9; k++) A2[k] = bc2(A2f[k]);
    #pragma unroll
    for (int k = 0; k < 3; k++) c2[k] = bc2(c2f[k]);
  }

  u64 s[9];
  #pragma unroll
  for (int k = 0; k < 9; k++) s[k] = 0ull;

  for (int it = 0; it < ITER; it++) {
    uint4 cu[3];
    if (it == 0) {
      #pragma unroll
      for (int c = 0; c < 3; c++) cu[c] = cu0[c];
    } else {
      int g  = base_g + it * 256 + threadIdx.x;
      int b  = g >> 14;
      int pg = (g & 16383) << 3;
      size_t po = (size_t)(b * NHEADS + head) * PLANE + pg;
      #pragma unroll
      for (int c = 0; c < 3; c++) cu[c] = __ldg((const uint4*)(src + po + c * CHSTRIDE));
    }
    #pragma unroll
    for (int w = 0; w < 4; w++) {
      u64 x0 = h2f2(pk_h(cu[0], w));
      u64 x1 = h2f2(pk_h(cu[1], w));
      u64 x2 = h2f2(pk_h(cu[2], w));
      affine_relu_f2(A1, c1, x0, x1, x2);
      if (S >= 2) affine_relu_f2(A2, c2, x0, x1, x2);
      mom_acc_f2(s, x0, x1, x2);
    }
  }
  block_reduce9_f2(s, S, lh);
}

// ---------------- final pass: inline full fold, both latents in f32x2 lanes ---
__global__ void __launch_bounds__(256) loss_kernel(
    const float* __restrict__ W1, const float* __restrict__ b1,
    const float* __restrict__ g1, const float* __restrict__ be1,
    const float* __restrict__ W2, const float* __restrict__ b2,
    const float* __restrict__ g2, const float* __restrict__ be2,
    const float* __restrict__ W3, const float* __restrict__ b3,
    const float* __restrict__ g3, const float* __restrict__ be3,
    const float* __restrict__ W4, const float* __restrict__ b4,
    const float* __restrict__ g4, const float* __restrict__ be4,
    const float* __restrict__ W5, const float* __restrict__ b5) {
  int bid = blockIdx.y * NB4 + blockIdx.x;
  bid = NB4 * NHEADS - 1 - bid;                 // reverse vs mH2 traversal
  int head = bid / NB4, bx = bid % NB4;

  const int GPB = GROUPS8 / NB4;         // 512
  const int ITER = GPB / 256;            // 2
  int base_g = bx * GPB;

  // issue first iteration's loads before the fold chain
  uint4 pk0[2][3];
  {
    int g = base_g + threadIdx.x;
    int b = g >> 14;
    int pg = (g & 16383) << 3;
    size_t po = (size_t)(b * NHEADS + head) * PLANE + pg;
    #pragma unroll
    for (int l = 0; l < 2; l++)
      #pragma unroll
      for (int c = 0; c < 3; c++)
        pk0[l][c] = __ldg((const uint4*)(d_x16[l] + po + c * CHSTRIDE));
  }

  // inline folds for both (latent, head) pairs (fp32, redundant per thread)
  float A1f[2][9], c1f[2][3], A2f[2][9], c2f[2][3], A3f[2][9], c3f[2][3], qf[2][3], rf[2];
  #pragma unroll
  for (int l = 0; l < 2; l++) {
    int lh = l * NHEADS + head;
    float m2[3], E2[9];
    fold_stage(d_mom[0][lh], W1, b1, g1, be1, head, A1f[l], c1f[l], nullptr, nullptr);
    fold_stage(d_mom[1][lh], W2, b2, g2, be2, head, A2f[l], c2f[l], nullptr, nullptr);
    fold_stage(d_mom[2][lh], W3, b3, g3, be3, head, A3f[l], c3f[l], m2, E2);
    fold_pred(A3f[l], c3f[l], m2, E2, W4, b4, g4, be4, head, qf[l], rf[l]);
  }

  u64 A1[9], c1[3], A2[9], c2[3], A3[9], c3[3], qv[3], rv;
  #pragma unroll
  for (int k = 0; k < 9; k++) {
    A1[k] = pk2(A1f[0][k], A1f[1][k]);
    A2[k] = pk2(A2f[0][k], A2f[1][k]);
    A3[k] = pk2(A3f[0][k], A3f[1][k]);
  }
  #pragma unroll
  for (int k = 0; k < 3; k++) {
    c1[k] = pk2(c1f[0][k], c1f[1][k]);
    c2[k] = pk2(c2f[0][k], c2f[1][k]);
    c3[k] = pk2(c3f[0][k], c3f[1][k]);
    qv[k] = pk2(qf[0][k], qf[1][k]);
  }
  rv = pk2(rf[0], rf[1]);

  float w5v[3], b5v[3];
  #pragma unroll
  for (int o = 0; o < 3; o++) { w5v[o] = W5[head * 3 + o]; b5v[o] = b5[head * 3 + o]; }
  float w55 = w5v[0] * w5v[0] + w5v[1] * w5v[1] + w5v[2] * w5v[2];
  float wb2 = 2.f * (w5v[0] * b5v[0] + w5v[1] * b5v[1] + w5v[2] * b5v[2]);
  float b55 = b5v[0] * b5v[0] + b5v[1] * b5v[1] + b5v[2] * b5v[2];

  float acc = 0.f;
  #pragma unroll
  for (int it = 0; it < ITER; it++) {
    uint4 pk[2][3];
    if (it == 0) {
      #pragma unroll
      for (int l = 0; l < 2; l++)
        #pragma unroll
        for (int c = 0; c < 3; c++) pk[l][c] = pk0[l][c];
    } else {
      int g  = base_g + it * 256 + threadIdx.x;
      int b  = g >> 14;
      int pg = (g & 16383) << 3;
      size_t po = (size_t)(b * NHEADS + head) * PLANE + pg;
      #pragma unroll
      for (int l = 0; l < 2; l++)
        #pragma unroll
        for (int c = 0; c < 3; c++)
          pk[l][c] = __ldg((const uint4*)(d_x16[l] + po + c * CHSTRIDE));
    }
    #pragma unroll
    for (int w = 0; w < 4; w++) {
      float2 fA[3], fB[3];
      #pragma unroll
      for (int c = 0; c < 3; c++) {
        fA[c] = __half22float2(pk_h(pk[0][c], w));
        fB[c] = __half22float2(pk_h(pk[1][c], w));
      }
      #pragma unroll
      for (int j = 0; j < 2; j++) {
        u64 x0 = pk2(j ? fA[0].y : fA[0].x, j ? fB[0].y : fB[0].x);
        u64 x1 = pk2(j ? fA[1].y : fA[1].x, j ? fB[1].y : fB[1].x);
        u64 x2 = pk2(j ? fA[2].y : fA[2].x, j ? fB[2].y : fB[2].x);
        affine_relu_f2(A1, c1, x0, x1, x2);
        affine_relu_f2(A2, c2, x0, x1, x2);
        u64 z0 = f2fma(A3[0], x0, f2fma(A3[1], x1, f2fma(A3[2], x2, c3[0])));
        u64 z1 = f2fma(A3[3], x0, f2fma(A3[4], x1, f2fma(A3[5], x2, c3[1])));
        u64 z2 = f2fma(A3[6], x0, f2fma(A3[7], x1, f2fma(A3[8], x2, c3[2])));
        u64 uv = f2fma(qv[0], z0, f2fma(qv[1], z1, f2fma(qv[2], z2, rv)));
        float za0, zb0, za1, zb1, za2, zb2, ua, ub;
        up2(z0, za0, zb0); up2(z1, za1, zb1); up2(z2, za2, zb2); up2(uv, ua, ub);
        float h4a = fmaxf(ua, 0.f), h4b = fmaxf(ub, 0.f);
        // cos(p1, z2): p1 = w5*h4a + b5 (latent1 pred vs latent2 proj)
        {
          float wz = w5v[0] * zb0 + w5v[1] * zb1 + w5v[2] * zb2;
          float bz = b5v[0] * zb0 + b5v[1] * zb1 + b5v[2] * zb2;
          float dot = fmaf(h4a, wz, bz);
          float pp = fmaf(fmaf(w55, h4a, wb2), h4a, b55);
          float zz = zb0 * zb0 + zb1 * zb1 + zb2 * zb2;
          acc = fmaf(dot, rsqrtf(fmaxf(pp * zz, 1e-16f)), acc);
        }
        // cos(p2, z1)
        {
          float wz = w5v[0] * za0 + w5v[1] * za1 + w5v[2] * za2;
          float bz = b5v[0] * za0 + b5v[1] * za1 + b5v[2] * za2;
          float dot = fmaf(h4b, wz, bz);
          float pp = fmaf(fmaf(w55, h4b, wb2), h4b, b55);
          float zz = za0 * za0 + za1 * za1 + za2 * za2;
          acc = fmaf(dot, rsqrtf(fmaxf(pp * zz, 1e-16f)), acc);
        }
      }
    }
  }

  #pragma unroll
  for (int o = 16; o > 0; o >>= 1) acc += __shfl_down_sync(0xffffffffu, acc, o);
  __shared__ float red[8];
  int warp = threadIdx.x >> 5, lane = threadIdx.x & 31;
  if (lane == 0) red[warp] = acc;
  __syncthreads();
  if (threadIdx.x == 0) {
    float t = 0.f;
    #pragma unroll
    for (int w = 0; w < 8; w++) t += red[w];
    atomicAdd(&d_loss, (double)t);
  }
}

// ---------------- writeout + state reset for next graph replay ---------------
__global__ void __launch_bounds__(256) writeout_kernel(float* out) {
  if (threadIdx.x == 0) {
    out[0] = (float)(d_loss * (-0.5 / NPIX_D));
    d_loss = 0.0;
  }
  double* p = &d_mom[0][0][0];
  for (int i = threadIdx.x; i < 3 * NLH * 9; i += 256) p[i] = 0.0;
}

// ---------------- launch ----------------
extern "C" void kernel_launch(void* const* d_in, const int* in_sizes, int n_in,
                              void* d_out, int out_size) {
  const float* lat1 = (const float*)d_in[0];
  const float* lat2 = (const float*)d_in[1];
  const float* W1 = (const float*)d_in[2];
  const float* b1 = (const float*)d_in[3];
  const float* g1 = (const float*)d_in[4];
  const float* be1 = (const float*)d_in[5];
  const float* W2 = (const float*)d_in[6];
  const float* b2 = (const float*)d_in[7];
  const float* g2 = (const float*)d_in[8];
  const float* be2 = (const float*)d_in[9];
  const float* W3 = (const float*)d_in[10];
  const float* b3 = (const float*)d_in[11];
  const float* g3 = (const float*)d_in[12];
  const float* be3 = (const float*)d_in[13];
  const float* W4 = (const float*)d_in[14];
  const float* b4 = (const float*)d_in[15];
  const float* g4 = (const float*)d_in[16];
  const float* be4 = (const float*)d_in[17];
  const float* W5 = (const float*)d_in[18];
  const float* b5 = (const float*)d_in[19];

  pass0_kernel<<<dim3(NB0, NLH), 256>>>(lat1, lat2);
  momentsH_kernel<1, true><<<dim3(NBS, NLH), 256>>>(W1, b1, g1, be1,
                                                    nullptr, nullptr, nullptr, nullptr);
  momentsH_kernel<2, false><<<dim3(NBS, NLH), 256>>>(W1, b1, g1, be1, W2, b2, g2, be2);
  loss_kernel<<<dim3(NB4, NHEADS), 256>>>(W1, b1, g1, be1, W2, b2, g2, be2,
                                          W3, b3, g3, be3, W4, b4, g4, be4, W5, b5);
  writeout_kernel<<<1, 256>>>((float*)d_out);
}

// round 13
// speedup vs baseline: 2.3334x; 2.3334x over previous
#include <cuda_runtime.h>
#include <cuda_fp16.h>
#include <math.h>

#define NHEADS   12
#define NLH      24          // (latent, head) pairs
#define CHSTRIDE 131072      // elems between channels within a (b,head) plane
#define PLANE    393216      // elems per (b,head) plane = 3*CHSTRIDE
#define LATELEMS 37748736    // elems per latent
#define NPIX_D   1048576.0   // pixels per head (8 * 131072)
#define GROUPS8  131072      // 8-pixel groups per (latent,head)
#define NB0      128         // blocks per (l,h) for pass0
#define NBS      128         // blocks per (l,h) for fp16 moments passes
#define NB4      256         // blocks per head for loss pass
#define BN_EPSF  1e-5f

typedef unsigned long long u64;

// ---------------- packed f32x2 helpers (Blackwell FFMA2 path) ----------------
__device__ __forceinline__ u64 pk2(float lo, float hi) {
  u64 r; asm("mov.b64 %0, {%1, %2};" : "=l"(r) : "f"(lo), "f"(hi)); return r;
}
__device__ __forceinline__ void up2(u64 v, float& lo, float& hi) {
  asm("mov.b64 {%0, %1}, %2;" : "=f"(lo), "=f"(hi) : "l"(v));
}
__device__ __forceinline__ u64 f2fma(u64 a, u64 b, u64 c) {
  u64 d; asm("fma.rn.f32x2 %0, %1, %2, %3;" : "=l"(d) : "l"(a), "l"(b), "l"(c)); return d;
}
__device__ __forceinline__ u64 f2add(u64 a, u64 b) {
  u64 d; asm("add.rn.f32x2 %0, %1, %2;" : "=l"(d) : "l"(a), "l"(b)); return d;
}
__device__ __forceinline__ u64 f2relu(u64 v) {
  float a, b; up2(v, a, b);
  return pk2(fmaxf(a, 0.f), fmaxf(b, 0.f));
}
__device__ __forceinline__ u64 h2f2(__half2 h) {
  float2 f = __half22float2(h); return pk2(f.x, f.y);
}
__device__ __forceinline__ u64 bc2(float f) { return pk2(f, f); }

// ---------------- device scratch (no allocation allowed) ----------------
// BSS zero-initialized at module load; writeout re-zeros for graph replays.
__device__ __align__(16) __half d_x16[2][LATELEMS];   // fp16 staged latents (151MB)
__device__ double d_mom[3][NLH][9];
__device__ float  d_Af[3][NLH][9];
__device__ float  d_cf[3][NLH][3];
__device__ float  d_qf[NLH][3];
__device__ float  d_rf[NLH];
__device__ double d_loss;

// ---------------- math helpers ----------------
__device__ __forceinline__ void affine_relu_f2(const u64* A, const u64* c,
                                               u64& x0, u64& x1, u64& x2) {
  u64 y0 = f2fma(A[0], x0, f2fma(A[1], x1, f2fma(A[2], x2, c[0])));
  u64 y1 = f2fma(A[3], x0, f2fma(A[4], x1, f2fma(A[5], x2, c[1])));
  u64 y2 = f2fma(A[6], x0, f2fma(A[7], x1, f2fma(A[8], x2, c[2])));
  x0 = f2relu(y0); x1 = f2relu(y1); x2 = f2relu(y2);
}

__device__ __forceinline__ void mom_acc_f2(u64* s, u64 x0, u64 x1, u64 x2) {
  s[0] = f2add(s[0], x0); s[1] = f2add(s[1], x1); s[2] = f2add(s[2], x2);
  s[3] = f2fma(x0, x0, s[3]); s[4] = f2fma(x0, x1, s[4]); s[5] = f2fma(x0, x2, s[5]);
  s[6] = f2fma(x1, x1, s[6]); s[7] = f2fma(x1, x2, s[7]); s[8] = f2fma(x2, x2, s[8]);
}

__device__ __forceinline__ void block_reduce9_f2(const u64* sp, int stage, int lh) {
  float s[9];
  #pragma unroll
  for (int k = 0; k < 9; k++) { float a, b; up2(sp[k], a, b); s[k] = a + b; }
  #pragma unroll
  for (int k = 0; k < 9; k++)
    #pragma unroll
    for (int o = 16; o > 0; o >>= 1) s[k] += __shfl_down_sync(0xffffffffu, s[k], o);
  __shared__ float red[8][9];
  int warp = threadIdx.x >> 5, lane = threadIdx.x & 31;
  if (lane == 0) {
    #pragma unroll
    for (int k = 0; k < 9; k++) red[warp][k] = s[k];
  }
  __syncthreads();
  if (threadIdx.x < 9) {
    float t = 0.f;
    #pragma unroll
    for (int w = 0; w < 8; w++) t += red[w][threadIdx.x];
    atomicAdd(&d_mom[stage][lh][threadIdx.x], (double)t);
  }
}

union Pk { uint4 u; __half2 h[4]; };
__device__ __forceinline__ __half2 pk_h(const uint4& u, int w) {
  Pk p; p.u = u; return p.h[w];
}

// ---------------- pass 0: fp32 read -> moments of x + fp16 stage-out ----------
__global__ void __launch_bounds__(256) pass0_kernel(const float* __restrict__ lat1,
                                                    const float* __restrict__ lat2) {
  int lh = blockIdx.y;
  int l = lh / NHEADS, head = lh - l * NHEADS;
  const float* __restrict__ src = l ? lat2 : lat1;
  __half* __restrict__ dst = d_x16[l];

  u64 s[9];
  #pragma unroll
  for (int k = 0; k < 9; k++) s[k] = 0ull;

  const int GPB = GROUPS8 / NB0;         // 1024
  const int ITER = GPB / 256;            // 4
  int base_g = blockIdx.x * GPB;

  for (int it = 0; it < ITER; it++) {
    int g  = base_g + it * 256 + threadIdx.x;
    int b  = g >> 14;
    int pg = (g & 16383) << 3;
    size_t po = (size_t)(b * NHEADS + head) * PLANE + pg;
    Pk pk[3];
    #pragma unroll
    for (int c = 0; c < 3; c++) {
      float4 v0 = __ldg((const float4*)(src + po + c * CHSTRIDE));
      float4 v1 = __ldg((const float4*)(src + po + c * CHSTRIDE + 4));
      pk[c].h[0] = __floats2half2_rn(v0.x, v0.y);
      pk[c].h[1] = __floats2half2_rn(v0.z, v0.w);
      pk[c].h[2] = __floats2half2_rn(v1.x, v1.y);
      pk[c].h[3] = __floats2half2_rn(v1.z, v1.w);
      *(uint4*)(dst + po + c * CHSTRIDE) = pk[c].u;
    }
    #pragma unroll
    for (int w = 0; w < 4; w++) {
      u64 x0 = h2f2(pk[0].h[w]);
      u64 x1 = h2f2(pk[1].h[w]);
      u64 x2 = h2f2(pk[2].h[w]);
      mom_acc_f2(s, x0, x1, x2);
    }
  }
  block_reduce9_f2(s, 0, lh);
}

// ---------------- fp16-data moments passes, f32x2 math ------------------------
// REV flips traversal so this pass starts on data the previous pass touched
// last (still L2-resident) -> zig-zag L2 reuse.
template <int S, bool REV>
__global__ void __launch_bounds__(256) momentsH_kernel() {
  int bid = blockIdx.y * NBS + blockIdx.x;
  if (REV) bid = NBS * NLH - 1 - bid;
  int lh = bid / NBS, bx = bid % NBS;
  const __half* __restrict__ src = d_x16[lh / NHEADS];
  int head = lh % NHEADS;

  u64 A1[9], c1[3], A2[9], c2[3];
  #pragma unroll
  for (int k = 0; k < 9; k++) A1[k] = bc2(d_Af[0][lh][k]);
  #pragma unroll
  for (int k = 0; k < 3; k++) c1[k] = bc2(d_cf[0][lh][k]);
  if (S >= 2) {
    #pragma unroll
    for (int k = 0; k < 9; k++) A2[k] = bc2(d_Af[1][lh][k]);
    #pragma unroll
    for (int k = 0; k < 3; k++) c2[k] = bc2(d_cf[1][lh][k]);
  }

  u64 s[9];
  #pragma unroll
  for (int k = 0; k < 9; k++) s[k] = 0ull;

  const int GPB = GROUPS8 / NBS;         // 1024
  const int ITER = GPB / 256;            // 4
  int base_g = bx * GPB;

  for (int it = 0; it < ITER; it++) {
    int g  = base_g + it * 256 + threadIdx.x;
    int b  = g >> 14;
    int pg = (g & 16383) << 3;
    size_t po = (size_t)(b * NHEADS + head) * PLANE + pg;
    uint4 cu[3];
    #pragma unroll
    for (int c = 0; c < 3; c++) cu[c] = __ldg((const uint4*)(src + po + c * CHSTRIDE));
    #pragma unroll
    for (int w = 0; w < 4; w++) {
      u64 x0 = h2f2(pk_h(cu[0], w));
      u64 x1 = h2f2(pk_h(cu[1], w));
      u64 x2 = h2f2(pk_h(cu[2], w));
      affine_relu_f2(A1, c1, x0, x1, x2);
      if (S >= 2) affine_relu_f2(A2, c2, x0, x1, x2);
      mom_acc_f2(s, x0, x1, x2);
    }
  }
  block_reduce9_f2(s, S, lh);
}

// ---------------- finalize: fp32 fold of conv+BN into affine ------------------
// fp32 (not fp64): ~15x shorter serial latency chain at 1 warp; accuracy
// validated in R12 (rel_err 2.2e-6 with fp32 fold).
template <int S>
__global__ void finalize_kernel(const float* __restrict__ W, const float* __restrict__ bb,
                                const float* __restrict__ g, const float* __restrict__ be,
                                const float* __restrict__ W4, const float* __restrict__ b4,
                                const float* __restrict__ g4, const float* __restrict__ be4) {
  int lh = threadIdx.x;
  if (lh >= NLH) return;
  int head = lh % NHEADS;
  const double inv = 1.0 / NPIX_D;
  float m[3], E[3][3];
  m[0] = (float)(d_mom[S][lh][0] * inv);
  m[1] = (float)(d_mom[S][lh][1] * inv);
  m[2] = (float)(d_mom[S][lh][2] * inv);
  E[0][0] = (float)(d_mom[S][lh][3] * inv);
  E[0][1] = E[1][0] = (float)(d_mom[S][lh][4] * inv);
  E[0][2] = E[2][0] = (float)(d_mom[S][lh][5] * inv);
  E[1][1] = (float)(d_mom[S][lh][6] * inv);
  E[1][2] = E[2][1] = (float)(d_mom[S][lh][7] * inv);
  E[2][2] = (float)(d_mom[S][lh][8] * inv);

  float A[3][3], cc[3];
  #pragma unroll
  for (int o = 0; o < 3; o++) {
    float w[3];
    #pragma unroll
    for (int c = 0; c < 3; c++) w[c] = W[head * 9 + o * 3 + c];
    float bl = bb[head * 3 + o];
    float wm = w[0] * m[0] + w[1] * m[1] + w[2] * m[2];
    float mo = wm + bl;
    float e2 = 0.f;
    #pragma unroll
    for (int c = 0; c < 3; c++)
      #pragma unroll
      for (int d = 0; d < 3; d++) e2 += w[c] * w[d] * E[c][d];
    e2 += 2.f * bl * wm + bl * bl;
    float v = e2 - mo * mo;
    float sc = g[head * 3 + o] * rsqrtf(v + BN_EPSF);
    #pragma unroll
    for (int c = 0; c < 3; c++) A[o][c] = sc * w[c];
    cc[o] = sc * (bl - mo) + be[head * 3 + o];
  }
  #pragma unroll
  for (int o = 0; o < 3; o++) {
    #pragma unroll
    for (int c = 0; c < 3; c++) d_Af[S][lh][o * 3 + c] = A[o][c];
    d_cf[S][lh][o] = cc[o];
  }

  if (S == 2) {
    // predictor pre-BN u = w4.z + b4 is linear in h2 -> stats from h2 moments
    float Amh[3], mz[3];
    #pragma unroll
    for (int o = 0; o < 3; o++) {
      Amh[o] = A[o][0] * m[0] + A[o][1] * m[1] + A[o][2] * m[2];
      mz[o] = Amh[o] + cc[o];
    }
    float Ezz[3][3];
    #pragma unroll
    for (int o = 0; o < 3; o++)
      #pragma unroll
      for (int p = 0; p < 3; p++) {
        float t = 0.f;
        #pragma unroll
        for (int c = 0; c < 3; c++)
          #pragma unroll
          for (int d = 0; d < 3; d++) t += A[o][c] * A[p][d] * E[c][d];
        Ezz[o][p] = t + cc[o] * Amh[p] + cc[p] * Amh[o] + cc[o] * cc[p];
      }
    float w4[3];
    #pragma unroll
    for (int c = 0; c < 3; c++) w4[c] = W4[head * 3 + c];
    float b4v = b4[head];
    float w4mz = w4[0] * mz[0] + w4[1] * mz[1] + w4[2] * mz[2];
    float mu = w4mz + b4v;
    float eu2 = 0.f;
    #pragma unroll
    for (int c = 0; c < 3; c++)
      #pragma unroll
      for (int d = 0; d < 3; d++) eu2 += w4[c] * w4[d] * Ezz[c][d];
    eu2 += 2.f * b4v * w4mz + b4v * b4v;
    float vu = eu2 - mu * mu;
    float s4 = g4[head] * rsqrtf(vu + BN_EPSF);
    #pragma unroll
    for (int c = 0; c < 3; c++) d_qf[lh][c] = s4 * w4[c];
    d_rf[lh] = s4 * (b4v - mu) + be4[head];
  }
}

// ---------------- final pass: both latents in the two f32x2 lanes -------------
// lane-low = latent1, lane-high = latent2; one packed network serves both views.
// Reverse traversal relative to momentsH<2> (forward) -> zig-zag L2 reuse.
__global__ void __launch_bounds__(256) loss_kernel(const float* __restrict__ W5,
                                                   const float* __restrict__ b5) {
  int bid = blockIdx.y * NB4 + blockIdx.x;
  bid = NB4 * NHEADS - 1 - bid;                 // reverse
  int head = bid / NB4, bx = bid % NB4;

  u64 A1[9], c1[3], A2[9], c2[3], A3[9], c3[3], qv[3], rv;
  #pragma unroll
  for (int k = 0; k < 9; k++) {
    A1[k] = pk2(d_Af[0][head][k], d_Af[0][NHEADS + head][k]);
    A2[k] = pk2(d_Af[1][head][k], d_Af[1][NHEADS + head][k]);
    A3[k] = pk2(d_Af[2][head][k], d_Af[2][NHEADS + head][k]);
  }
  #pragma unroll
  for (int k = 0; k < 3; k++) {
    c1[k] = pk2(d_cf[0][head][k], d_cf[0][NHEADS + head][k]);
    c2[k] = pk2(d_cf[1][head][k], d_cf[1][NHEADS + head][k]);
    c3[k] = pk2(d_cf[2][head][k], d_cf[2][NHEADS + head][k]);
    qv[k] = pk2(d_qf[head][k], d_qf[NHEADS + head][k]);
  }
  rv = pk2(d_rf[head], d_rf[NHEADS + head]);

  float w5v[3], b5v[3];
  #pragma unroll
  for (int o = 0; o < 3; o++) { w5v[o] = W5[head * 3 + o]; b5v[o] = b5[head * 3 + o]; }
  float w55 = w5v[0] * w5v[0] + w5v[1] * w5v[1] + w5v[2] * w5v[2];
  float wb2 = 2.f * (w5v[0] * b5v[0] + w5v[1] * b5v[1] + w5v[2] * b5v[2]);
  float b55 = b5v[0] * b5v[0] + b5v[1] * b5v[1] + b5v[2] * b5v[2];

  float acc = 0.f;
  const int GPB = GROUPS8 / NB4;         // 512
  const int ITER = GPB / 256;            // 2
  int base_g = bx * GPB;

  #pragma unroll
  for (int it = 0; it < ITER; it++) {
    int g  = base_g + it * 256 + threadIdx.x;
    int b  = g >> 14;
    int pg = (g & 16383) << 3;
    size_t po = (size_t)(b * NHEADS + head) * PLANE + pg;
    uint4 pk[2][3];
    #pragma unroll
    for (int l = 0; l < 2; l++)
      #pragma unroll
      for (int c = 0; c < 3; c++)
        pk[l][c] = __ldg((const uint4*)(d_x16[l] + po + c * CHSTRIDE));
    #pragma unroll
    for (int w = 0; w < 4; w++) {
      float2 fA[3], fB[3];
      #pragma unroll
      for (int c = 0; c < 3; c++) {
        fA[c] = __half22float2(pk_h(pk[0][c], w));
        fB[c] = __half22float2(pk_h(pk[1][c], w));
      }
      #pragma unroll
      for (int j = 0; j < 2; j++) {
        u64 x0 = pk2(j ? fA[0].y : fA[0].x, j ? fB[0].y : fB[0].x);
        u64 x1 = pk2(j ? fA[1].y : fA[1].x, j ? fB[1].y : fB[1].x);
        u64 x2 = pk2(j ? fA[2].y : fA[2].x, j ? fB[2].y : fB[2].x);
        affine_relu_f2(A1, c1, x0, x1, x2);
        affine_relu_f2(A2, c2, x0, x1, x2);
        u64 z0 = f2fma(A3[0], x0, f2fma(A3[1], x1, f2fma(A3[2], x2, c3[0])));
        u64 z1 = f2fma(A3[3], x0, f2fma(A3[4], x1, f2fma(A3[5], x2, c3[1])));
        u64 z2 = f2fma(A3[6], x0, f2fma(A3[7], x1, f2fma(A3[8], x2, c3[2])));
        u64 uv = f2fma(qv[0], z0, f2fma(qv[1], z1, f2fma(qv[2], z2, rv)));
        float za0, zb0, za1, zb1, za2, zb2, ua, ub;
        up2(z0, za0, zb0); up2(z1, za1, zb1); up2(z2, za2, zb2); up2(uv, ua, ub);
        float h4a = fmaxf(ua, 0.f), h4b = fmaxf(ub, 0.f);
        // cos(p1, z2): p1 = w5*h4a + b5 (latent1 pred vs latent2 proj)
        {
          float wz = w5v[0] * zb0 + w5v[1] * zb1 + w5v[2] * zb2;
          float bz = b5v[0] * zb0 + b5v[1] * zb1 + b5v[2] * zb2;
          float dot = fmaf(h4a, wz, bz);
          float pp = fmaf(fmaf(w55, h4a, wb2), h4a, b55);
          float zz = zb0 * zb0 + zb1 * zb1 + zb2 * zb2;
          acc = fmaf(dot, rsqrtf(fmaxf(pp * zz, 1e-16f)), acc);
        }
        // cos(p2, z1)
        {
          float wz = w5v[0] * za0 + w5v[1] * za1 + w5v[2] * za2;
          float bz = b5v[0] * za0 + b5v[1] * za1 + b5v[2] * za2;
          float dot = fmaf(h4b, wz, bz);
          float pp = fmaf(fmaf(w55, h4b, wb2), h4b, b55);
          float zz = za0 * za0 + za1 * za1 + za2 * za2;
          acc = fmaf(dot, rsqrtf(fmaxf(pp * zz, 1e-16f)), acc);
        }
      }
    }
  }

  #pragma unroll
  for (int o = 16; o > 0; o >>= 1) acc += __shfl_down_sync(0xffffffffu, acc, o);
  __shared__ float red[8];
  int warp = threadIdx.x >> 5, lane = threadIdx.x & 31;
  if (lane == 0) red[warp] = acc;
  __syncthreads();
  if (threadIdx.x == 0) {
    float t = 0.f;
    #pragma unroll
    for (int w = 0; w < 8; w++) t += red[w];
    atomicAdd(&d_loss, (double)t);
  }
}

// ---------------- writeout + state reset for next graph replay ---------------
__global__ void __launch_bounds__(256) writeout_kernel(float* out) {
  if (threadIdx.x == 0) {
    out[0] = (float)(d_loss * (-0.5 / NPIX_D));
    d_loss = 0.0;
  }
  double* p = &d_mom[0][0][0];
  for (int i = threadIdx.x; i < 3 * NLH * 9; i += 256) p[i] = 0.0;
}

// ---------------- launch ----------------
extern "C" void kernel_launch(void* const* d_in, const int* in_sizes, int n_in,
                              void* d_out, int out_size) {
  const float* lat1 = (const float*)d_in[0];
  const float* lat2 = (const float*)d_in[1];
  const float* W1 = (const float*)d_in[2];
  const float* b1 = (const float*)d_in[3];
  const float* g1 = (const float*)d_in[4];
  const float* be1 = (const float*)d_in[5];
  const float* W2 = (const float*)d_in[6];
  const float* b2 = (const float*)d_in[7];
  const float* g2 = (const float*)d_in[8];
  const float* be2 = (const float*)d_in[9];
  const float* W3 = (const float*)d_in[10];
  const float* b3 = (const float*)d_in[11];
  const float* g3 = (const float*)d_in[12];
  const float* be3 = (const float*)d_in[13];
  const float* W4 = (const float*)d_in[14];
  const float* b4 = (const float*)d_in[15];
  const float* g4 = (const float*)d_in[16];
  const float* be4 = (const float*)d_in[17];
  const float* W5 = (const float*)d_in[18];
  const float* b5 = (const float*)d_in[19];

  pass0_kernel<<<dim3(NB0, NLH), 256>>>(lat1, lat2);
  finalize_kernel<0><<<1, 32>>>(W1, b1, g1, be1, nullptr, nullptr, nullptr, nullptr);
  momentsH_kernel<1, true><<<dim3(NBS, NLH), 256>>>();   // reverse vs pass0 writes
  finalize_kernel<1><<<1, 32>>>(W2, b2, g2, be2, nullptr, nullptr, nullptr, nullptr);
  momentsH_kernel<2, false><<<dim3(NBS, NLH), 256>>>();  // forward (reverse vs mH1)
  finalize_kernel<2><<<1, 32>>>(W3, b3, g3, be3, W4, b4, g4, be4);
  loss_kernel<<<dim3(NB4, NHEADS), 256>>>(W5, b5);       // reverse vs mH2
  writeout_kernel<<<1, 256>>>((float*)d_out);
}